// round 6
// baseline (speedup 1.0000x reference)
#include <cuda_runtime.h>

#define NB 64
#define NC 3
#define NH 96
#define NW 320
#define NHW (NH*NW)
#define K_TOP 50
#define CAND_CAP 4608
#define DIRECT_MAX 1024
#define SBUF 512
#define FCAP 1024
#define THETA 0.99f
#define DET_TH 0.25f
#define PI_F 3.14159265f
#define NSTRIPS (NH*(NW/8))   // 3840 strips of 8 pixels

typedef unsigned long long ull;

// one packed u64 per (channel, rank): (f2k(value)<<32) | ~pixel_idx
__device__ ull g_pk[NB*NC*K_TOP];

// order-preserving float->uint key (ascending float -> ascending uint)
__device__ __forceinline__ unsigned f2k(float f){
    unsigned b = __float_as_uint(f);
    return (b & 0x80000000u) ? ~b : (b | 0x80000000u);
}
__device__ __forceinline__ float k2f(unsigned k){
    return (k & 0x80000000u) ? __uint_as_float(k ^ 0x80000000u) : __uint_as_float(~k);
}

// full 3x3 NMS test for one 8-pixel strip; returns bitmask of peaks > theta
__device__ __forceinline__ unsigned strip_mask(const float* __restrict__ h,
                                               int y, int x0, float theta){
    int yA = y > 0      ? y - 1 : 0;
    int yB = y < NH - 1 ? y + 1 : NH - 1;
    const float* r0 = h + yA * NW;
    const float* r1 = h + y  * NW;
    const float* r2 = h + yB * NW;
    float4 a0 = *(const float4*)(r0 + x0); float4 b0 = *(const float4*)(r0 + x0 + 4);
    float4 a1 = *(const float4*)(r1 + x0); float4 b1 = *(const float4*)(r1 + x0 + 4);
    float4 a2 = *(const float4*)(r2 + x0); float4 b2 = *(const float4*)(r2 + x0 + 4);
    float c[8] = {a1.x, a1.y, a1.z, a1.w, b1.x, b1.y, b1.z, b1.w};
    float vm[10];
    vm[1] = fmaxf(fmaxf(a0.x, a1.x), a2.x);
    vm[2] = fmaxf(fmaxf(a0.y, a1.y), a2.y);
    vm[3] = fmaxf(fmaxf(a0.z, a1.z), a2.z);
    vm[4] = fmaxf(fmaxf(a0.w, a1.w), a2.w);
    vm[5] = fmaxf(fmaxf(b0.x, b1.x), b2.x);
    vm[6] = fmaxf(fmaxf(b0.y, b1.y), b2.y);
    vm[7] = fmaxf(fmaxf(b0.z, b1.z), b2.z);
    vm[8] = fmaxf(fmaxf(b0.w, b1.w), b2.w);
    vm[0] = (x0 > 0)      ? fmaxf(fmaxf(r0[x0-1], r1[x0-1]), r2[x0-1]) : -1e30f;
    vm[9] = (x0 + 8 < NW) ? fmaxf(fmaxf(r0[x0+8], r1[x0+8]), r2[x0+8]) : -1e30f;
    unsigned msk = 0u;
    #pragma unroll
    for (int j = 0; j < 8; j++){
        float hm = fmaxf(fmaxf(vm[j], vm[j+1]), vm[j+2]);
        if (c[j] == hm && c[j] > theta) msk |= (1u << j);
    }
    return msk;
}

// ---------------------------------------------------------------------------
// Kernel 1: screened 3x3 NMS + exact top-50 per (batch, channel).
// A1: pure screen (2 LDG.128 + max8), flagged strip-ids -> shared list.
// A2: dense heavy pass over ~300 flagged strips only (full warps active).
// Guards: flist overflow OR cnt<50 -> full unscreened rescan (never taken
// for this data; preserves exactness for any input).
// ---------------------------------------------------------------------------
__global__ __launch_bounds__(512) void nms_topk_kernel(const float* __restrict__ heat){
    __shared__ ull      ck[CAND_CAP];
    __shared__ union { ull sk[SBUF]; int flist[FCAP]; } u;   // disjoint lifetimes
    __shared__ unsigned hist[256];
    __shared__ int cnt, scnt, fcnt;
    __shared__ unsigned s_prefix;
    __shared__ int s_remaining, s_total;

    const int bc = blockIdx.x;
    const float* __restrict__ h = heat + (size_t)bc * NHW;
    const int t = threadIdx.x;
    const int lane = t & 31;

    if (t == 0){ cnt = 0; scnt = 0; fcnt = 0; s_prefix = 0u; s_remaining = K_TOP; s_total = 0; }
    __syncthreads();

    // ---- A1: screen all strips, compact flagged ids ---------------------
    #pragma unroll 1
    for (int item = t; item < NSTRIPS; item += 512){    // boundary warp-uniform
        int y  = item / 40;                             // 40 = NW/8
        int x0 = (item - y * 40) * 8;
        const float* r1 = h + y * NW;
        float4 a1 = *(const float4*)(r1 + x0);
        float4 b1 = *(const float4*)(r1 + x0 + 4);
        float m8 = fmaxf(fmaxf(fmaxf(a1.x, a1.y), fmaxf(a1.z, a1.w)),
                         fmaxf(fmaxf(b1.x, b1.y), fmaxf(b1.z, b1.w)));
        bool flag = m8 > THETA;
        unsigned bal = __ballot_sync(0xFFFFFFFFu, flag);
        if (bal){
            int ldr = __ffs(bal) - 1, base = 0;
            if (lane == ldr) base = atomicAdd(&fcnt, __popc(bal));
            base = __shfl_sync(0xFFFFFFFFu, base, ldr);
            if (flag){
                int p = base + __popc(bal & ((1u << lane) - 1u));
                if (p < FCAP) u.flist[p] = item;
            }
        }
    }
    __syncthreads();

    // ---- A2: heavy pass on flagged strips only --------------------------
    bool need_full = (fcnt > FCAP);
    if (!need_full){
        int fc = fcnt;
        #pragma unroll 1
        for (int i = t; i < fc; i += 512){
            int item = u.flist[i];
            int y  = item / 40;
            int x0 = (item - y * 40) * 8;
            unsigned msk = strip_mask(h, y, x0, THETA);
            if (msk){
                int pos = atomicAdd(&cnt, __popc(msk));
                int base = y * NW + x0;
                while (msk){
                    int j = __ffs(msk) - 1; msk &= msk - 1;
                    if (pos < CAND_CAP)
                        ck[pos] = ((ull)f2k(h[base + j]) << 32) | (unsigned)~(base + j);
                    pos++;
                }
            }
        }
        __syncthreads();
        need_full = (cnt < K_TOP);   // screened set provably complete iff cnt>=50
    }

    // ---- fallback: full unscreened scan (correctness guard) -------------
    if (need_full){
        if (t == 0) cnt = 0;
        __syncthreads();
        #pragma unroll 1
        for (int item = t; item < NSTRIPS; item += 512){
            int y  = item / 40;
            int x0 = (item - y * 40) * 8;
            unsigned msk = strip_mask(h, y, x0, -1e30f);
            if (msk){
                int pos = atomicAdd(&cnt, __popc(msk));
                int base = y * NW + x0;
                while (msk){
                    int j = __ffs(msk) - 1; msk &= msk - 1;
                    if (pos < CAND_CAP)
                        ck[pos] = ((ull)f2k(h[base + j]) << 32) | (unsigned)~(base + j);
                    pos++;
                }
            }
        }
        __syncthreads();
    }

    int n = min(cnt, CAND_CAP);
    const ull* src = ck;
    int m = n;

    if (n > DIRECT_MAX){
        // ---- radix-select fallback (rare) -------------------------------
        unsigned prefix = 0u;
        int shift = 24;
        #pragma unroll 1
        for (int pass = 0; pass < 4; pass++){
            if (t < 256) hist[t] = 0u;
            __syncthreads();
            for (int j = t; j < n; j += 512){
                unsigned key = (unsigned)(ck[j] >> 32);
                bool act = (pass == 0) || ((key >> (shift + 8)) == prefix);
                if (act) atomicAdd(&hist[(key >> shift) & 255u], 1u);
            }
            __syncthreads();
            if (t == 0){
                int rem = s_remaining;
                int cum = 0, d = 255;
                for (int dd = 255; dd >= 0; dd--){
                    cum += (int)hist[dd];
                    if (cum >= rem){ d = dd; break; }
                }
                int above_inc = cum - (int)hist[d];
                s_total     = (K_TOP - rem) + cum;
                s_remaining = rem - above_inc;
                s_prefix    = (s_prefix << 8) | (unsigned)d;
            }
            __syncthreads();
            prefix = s_prefix;
            if (s_total <= SBUF || shift == 0) break;
            shift -= 8;
        }
        for (int j = t; j < n; j += 512){
            ull p = ck[j];
            if (((unsigned)(p >> 32) >> shift) >= prefix){
                int q = atomicAdd(&scnt, 1);
                if (q < SBUF) u.sk[q] = p;
            }
        }
        __syncthreads();
        src = u.sk; m = min(scnt, SBUF);
    }

    // pad output slots, then exact parallel rank (value desc, idx asc)
    if (t < K_TOP) g_pk[bc * K_TOP + t] = ((ull)0x80000000u << 32) | 0xFFFFFFFFull;
    __syncthreads();
    for (int i = t; i < m; i += 512){
        ull mine = src[i];
        int r = 0;
        for (int jj = 0; jj < m; jj++) r += (src[jj] > mine);   // smem broadcast
        if (r < K_TOP) g_pk[bc * K_TOP + r] = mine;
    }
}

// ---------------------------------------------------------------------------
// Kernel 2: per-batch parallel 3-way rank-merge + cooperative regression
// gather + per-detection geometry.
// Merge ranks on VALUE ONLY; ties -> lower flat position (== lax.top_k
// stage-2 over the channel-major (C*TOPK) array).
// ---------------------------------------------------------------------------
__device__ __forceinline__ void inv3(const float* __restrict__ A, float* Ai){
    float a = A[0], b = A[1], c = A[2];
    float d = A[3], e = A[4], f = A[5];
    float g = A[6], h = A[7], i = A[8];
    float A00 = e*i - f*h, A01 = c*h - b*i, A02 = b*f - c*e;
    float A10 = f*g - d*i, A11 = a*i - c*g, A12 = c*d - a*f;
    float A20 = d*h - e*g, A21 = b*g - a*h, A22 = a*e - b*d;
    float r = 1.0f / (a*A00 + b*A10 + c*A20);
    Ai[0] = A00*r; Ai[1] = A01*r; Ai[2] = A02*r;
    Ai[3] = A10*r; Ai[4] = A11*r; Ai[5] = A12*r;
    Ai[6] = A20*r; Ai[7] = A21*r; Ai[8] = A22*r;
}

__device__ __forceinline__ float wrap_pi(float a){
    return a > PI_F ? a - 2.0f*PI_F : (a < -PI_F ? a + 2.0f*PI_F : a);
}

__global__ __launch_bounds__(192) void merge_geom_kernel(const float* __restrict__ regr,
                                                         const float* __restrict__ calib,
                                                         const float* __restrict__ trans,
                                                         const float* __restrict__ dimref,
                                                         float* __restrict__ out){
    __shared__ ull spk[NC*K_TOP];
    __shared__ ull rpk[K_TOP];            // ranked: (key<<32)|(cls<<20)|idx
    __shared__ float sreg[K_TOP][13];     // 12 comps, padded -> conflict-free
    const int b = blockIdx.x;
    const int t = threadIdx.x;

    if (t < NC*K_TOP) spk[t] = g_pk[b * NC * K_TOP + t];
    __syncthreads();

    if (t < NC*K_TOP){
        ull mine = spk[t];
        unsigned mk = (unsigned)(mine >> 32);      // value key only
        int r = 0;
        #pragma unroll 10
        for (int jj = 0; jj < NC*K_TOP; jj++){
            unsigned ok = (unsigned)(spk[jj] >> 32);
            r += (ok > mk) || (ok == mk && jj < t);  // flat-position tie-break
        }
        if (r < K_TOP){
            int cls = t / K_TOP;
            unsigned idx = ~((unsigned)mine);          // pixel index (< 2^20)
            rpk[r] = ((ull)mk << 32) | ((unsigned)cls << 20) | idx;
        }
    }
    __syncthreads();

    // cooperative gather: 50 dets x 12 comps, all 192 threads -> high MLP
    #pragma unroll 1
    for (int q = t; q < K_TOP * 12; q += 192){
        int det  = q / 12;
        int comp = q - det * 12;
        ull p = rpk[det];
        float score = k2f((unsigned)(p >> 32));
        if (score > DET_TH){
            int hw = (int)(p & 0xFFFFFu);
            sreg[det][comp] = __ldg(regr + ((size_t)b * 12 + comp) * NHW + hw);
        }
    }
    __syncthreads();

    if (t < K_TOP){
        const int det = b * K_TOP + t;
        ull p = rpk[t];
        float score = k2f((unsigned)(p >> 32));
        float* o = out + (size_t)det * 14;

        if (!(score > DET_TH)){
            #pragma unroll
            for (int i = 0; i < 14; i++) o[i] = 0.0f;
        } else {
            int cls = (int)((p >> 20) & 3u);
            int hw  = (int)(p & 0xFFFFFu);
            float xs = (float)(hw % NW);
            float ys = (float)(hw / NW);

            float reg[12];
            #pragma unroll
            for (int r = 0; r < 12; r++) reg[r] = sreg[t][r];

            float Ti[9], Ki[9], Tm[9], Km[9];
            #pragma unroll
            for (int i = 0; i < 9; i++){ Tm[i] = __ldg(trans + b*9 + i); Km[i] = __ldg(calib + b*9 + i); }
            inv3(Tm, Ti);
            inv3(Km, Ki);

            float depth = reg[0] * 16.32f + 28.01f;
            float px = xs + reg[1], py = ys + reg[2];
            float t0 = (Ti[0]*px + Ti[1]*py + Ti[2]) * depth;
            float t1 = (Ti[3]*px + Ti[4]*py + Ti[5]) * depth;
            float t2 = (Ti[6]*px + Ti[7]*py + Ti[8]) * depth;
            float l0 = Ki[0]*t0 + Ki[1]*t1 + Ki[2]*t2;
            float l1 = Ki[3]*t0 + Ki[4]*t1 + Ki[5]*t2;
            float l2 = Ki[6]*t0 + Ki[7]*t1 + Ki[8]*t2;

            float d0 = expf(reg[3]) * __ldg(dimref + cls*3 + 0);
            float d1 = expf(reg[4]) * __ldg(dimref + cls*3 + 1);
            float d2 = expf(reg[5]) * __ldg(dimref + cls*3 + 2);
            l1 += d1 * 0.5f;

            float ray   = atanf(l0 / (l2 + 1e-7f));
            float alpha = atanf(reg[6] / (reg[7] + 1e-7f));
            alpha += (reg[7] >= 0.0f) ? -PI_F*0.5f : PI_F*0.5f;
            float roty = wrap_pi(alpha + ray);     // pre-wrap alpha, per ref
            alpha = wrap_pi(alpha);

            float cx = xs + reg[8], cy = ys + reg[9];
            float ltx = cx - reg[10]*0.5f, lty = cy - reg[11]*0.5f;
            float rbx = cx + reg[10]*0.5f, rby = cy + reg[11]*0.5f;
            float b0 = Ti[0]*ltx + Ti[1]*lty + Ti[2];
            float b1 = Ti[3]*ltx + Ti[4]*lty + Ti[5];
            float b2 = Ti[0]*rbx + Ti[1]*rby + Ti[2];
            float b3 = Ti[3]*rbx + Ti[4]*rby + Ti[5];

            o[0]  = (float)cls;
            o[1]  = alpha;
            o[2]  = b0; o[3] = b1; o[4] = b2; o[5] = b3;
            o[6]  = d1; o[7] = d2; o[8] = d0;      // roll(dims3d, -1)
            o[9]  = l0; o[10] = l1; o[11] = l2;
            o[12] = roty;
            o[13] = score;
        }
    }
}

// ---------------------------------------------------------------------------
extern "C" void kernel_launch(void* const* d_in, const int* in_sizes, int n_in,
                              void* d_out, int out_size){
    const float* heat   = (const float*)d_in[0];
    const float* regr   = (const float*)d_in[1];
    const float* calib  = (const float*)d_in[2];
    const float* trans  = (const float*)d_in[3];
    const float* dimref = (const float*)d_in[4];
    float* out = (float*)d_out;

    nms_topk_kernel<<<NB * NC, 512>>>(heat);
    merge_geom_kernel<<<NB, 192>>>(regr, calib, trans, dimref, out);
}

// round 7
// speedup vs baseline: 1.0722x; 1.0722x over previous
#include <cuda_runtime.h>

#define NB 64
#define NC 3
#define NH 96
#define NW 320
#define NHW (NH*NW)
#define K_TOP 50
#define CAND_CAP 4608
#define DIRECT_MAX 1024
#define SBUF 512
#define FCAP 512
#define THETA 0.99f
#define DET_TH 0.25f
#define PI_F 3.14159265f
#define NSTRIPS (NH*(NW/8))   // 3840 strips of 8 pixels
#define NT 1024

typedef unsigned long long ull;

// one packed u64 per (channel, rank): (f2k(value)<<32) | ~pixel_idx
__device__ ull g_pk[NB*NC*K_TOP];
// per-batch arrival counters (zero-init at load; each launch resets its own)
__device__ int g_bar[NB];

// order-preserving float->uint key (ascending float -> ascending uint)
__device__ __forceinline__ unsigned f2k(float f){
    unsigned b = __float_as_uint(f);
    return (b & 0x80000000u) ? ~b : (b | 0x80000000u);
}
__device__ __forceinline__ float k2f(unsigned k){
    return (k & 0x80000000u) ? __uint_as_float(k ^ 0x80000000u) : __uint_as_float(~k);
}

// full 3x3 NMS test for one 8-pixel strip; returns bitmask of peaks > theta
__device__ __forceinline__ unsigned strip_mask(const float* __restrict__ h,
                                               int y, int x0, float theta){
    int yA = y > 0      ? y - 1 : 0;
    int yB = y < NH - 1 ? y + 1 : NH - 1;
    const float* r0 = h + yA * NW;
    const float* r1 = h + y  * NW;
    const float* r2 = h + yB * NW;
    float4 a0 = *(const float4*)(r0 + x0); float4 b0 = *(const float4*)(r0 + x0 + 4);
    float4 a1 = *(const float4*)(r1 + x0); float4 b1 = *(const float4*)(r1 + x0 + 4);
    float4 a2 = *(const float4*)(r2 + x0); float4 b2 = *(const float4*)(r2 + x0 + 4);
    float c[8] = {a1.x, a1.y, a1.z, a1.w, b1.x, b1.y, b1.z, b1.w};
    float vm[10];
    vm[1] = fmaxf(fmaxf(a0.x, a1.x), a2.x);
    vm[2] = fmaxf(fmaxf(a0.y, a1.y), a2.y);
    vm[3] = fmaxf(fmaxf(a0.z, a1.z), a2.z);
    vm[4] = fmaxf(fmaxf(a0.w, a1.w), a2.w);
    vm[5] = fmaxf(fmaxf(b0.x, b1.x), b2.x);
    vm[6] = fmaxf(fmaxf(b0.y, b1.y), b2.y);
    vm[7] = fmaxf(fmaxf(b0.z, b1.z), b2.z);
    vm[8] = fmaxf(fmaxf(b0.w, b1.w), b2.w);
    vm[0] = (x0 > 0)      ? fmaxf(fmaxf(r0[x0-1], r1[x0-1]), r2[x0-1]) : -1e30f;
    vm[9] = (x0 + 8 < NW) ? fmaxf(fmaxf(r0[x0+8], r1[x0+8]), r2[x0+8]) : -1e30f;
    unsigned msk = 0u;
    #pragma unroll
    for (int j = 0; j < 8; j++){
        float hm = fmaxf(fmaxf(vm[j], vm[j+1]), vm[j+2]);
        if (c[j] == hm && c[j] > theta) msk |= (1u << j);
    }
    return msk;
}

__device__ __forceinline__ void inv3(const float* __restrict__ A, float* Ai){
    float a = A[0], b = A[1], c = A[2];
    float d = A[3], e = A[4], f = A[5];
    float g = A[6], h = A[7], i = A[8];
    float A00 = e*i - f*h, A01 = c*h - b*i, A02 = b*f - c*e;
    float A10 = f*g - d*i, A11 = a*i - c*g, A12 = c*d - a*f;
    float A20 = d*h - e*g, A21 = b*g - a*h, A22 = a*e - b*d;
    float r = 1.0f / (a*A00 + b*A10 + c*A20);
    Ai[0] = A00*r; Ai[1] = A01*r; Ai[2] = A02*r;
    Ai[3] = A10*r; Ai[4] = A11*r; Ai[5] = A12*r;
    Ai[6] = A20*r; Ai[7] = A21*r; Ai[8] = A22*r;
}

__device__ __forceinline__ float wrap_pi(float a){
    return a > PI_F ? a - 2.0f*PI_F : (a < -PI_F ? a + 2.0f*PI_F : a);
}

// ---------------------------------------------------------------------------
// Fused kernel: one CTA per (batch, channel).
// Stage 1: screened 3x3 NMS + exact per-channel top-50 -> g_pk.
// Stage 2: the LAST of a batch's 3 CTAs to arrive runs the 3-way rank-merge
//          + regression gather + geometry for that batch (no second launch).
// ---------------------------------------------------------------------------
__global__ __launch_bounds__(NT) void postproc_kernel(const float* __restrict__ heat,
                                                      const float* __restrict__ regr,
                                                      const float* __restrict__ calib,
                                                      const float* __restrict__ trans,
                                                      const float* __restrict__ dimref,
                                                      float* __restrict__ out){
    __shared__ ull      ck[CAND_CAP];
    __shared__ union { ull sk[SBUF]; int flist[FCAP]; } u;   // disjoint lifetimes
    __shared__ unsigned hist[256];
    __shared__ int cnt, scnt, fcnt, s_arrive;
    __shared__ unsigned s_prefix;
    __shared__ int s_remaining, s_total;
    __shared__ ull spk[NC*K_TOP];
    __shared__ ull rpk[K_TOP];            // (key<<32)|(cls<<20)|idx
    __shared__ float sreg[K_TOP][13];     // padded: conflict-free

    const int bc = blockIdx.x;            // b*NC + c
    const int b  = bc / NC;
    const float* __restrict__ h = heat + (size_t)bc * NHW;
    const int t = threadIdx.x;
    const int lane = t & 31;

    if (t == 0){ cnt = 0; scnt = 0; fcnt = 0; s_prefix = 0u; s_remaining = K_TOP; s_total = 0; }
    __syncthreads();

    // ---- A1: screen all strips, compact flagged ids ---------------------
    #pragma unroll 1
    for (int item = t; item < NSTRIPS; item += NT){     // exits warp-uniform
        int y  = item / 40;                             // 40 = NW/8
        int x0 = (item - y * 40) * 8;
        const float* r1 = h + y * NW;
        float4 a1 = *(const float4*)(r1 + x0);
        float4 b1 = *(const float4*)(r1 + x0 + 4);
        float m8 = fmaxf(fmaxf(fmaxf(a1.x, a1.y), fmaxf(a1.z, a1.w)),
                         fmaxf(fmaxf(b1.x, b1.y), fmaxf(b1.z, b1.w)));
        bool flag = m8 > THETA;
        unsigned bal = __ballot_sync(0xFFFFFFFFu, flag);
        if (bal){
            int ldr = __ffs(bal) - 1, base = 0;
            if (lane == ldr) base = atomicAdd(&fcnt, __popc(bal));
            base = __shfl_sync(0xFFFFFFFFu, base, ldr);
            if (flag){
                int p = base + __popc(bal & ((1u << lane) - 1u));
                if (p < FCAP) u.flist[p] = item;
            }
        }
    }
    __syncthreads();

    // ---- A2: heavy pass on flagged strips only --------------------------
    bool need_full = (fcnt > FCAP);
    if (!need_full){
        int fc = fcnt;
        #pragma unroll 1
        for (int i = t; i < fc; i += NT){
            int item = u.flist[i];
            int y  = item / 40;
            int x0 = (item - y * 40) * 8;
            unsigned msk = strip_mask(h, y, x0, THETA);
            if (msk){
                int pos = atomicAdd(&cnt, __popc(msk));
                int base = y * NW + x0;
                while (msk){
                    int j = __ffs(msk) - 1; msk &= msk - 1;
                    if (pos < CAND_CAP)
                        ck[pos] = ((ull)f2k(h[base + j]) << 32) | (unsigned)~(base + j);
                    pos++;
                }
            }
        }
        __syncthreads();
        need_full = (cnt < K_TOP);   // screened set provably complete iff cnt>=50
    }

    // ---- fallback: full unscreened scan (correctness guard) -------------
    if (need_full){
        if (t == 0) cnt = 0;
        __syncthreads();
        #pragma unroll 1
        for (int item = t; item < NSTRIPS; item += NT){
            int y  = item / 40;
            int x0 = (item - y * 40) * 8;
            unsigned msk = strip_mask(h, y, x0, -1e30f);
            if (msk){
                int pos = atomicAdd(&cnt, __popc(msk));
                int base = y * NW + x0;
                while (msk){
                    int j = __ffs(msk) - 1; msk &= msk - 1;
                    if (pos < CAND_CAP)
                        ck[pos] = ((ull)f2k(h[base + j]) << 32) | (unsigned)~(base + j);
                    pos++;
                }
            }
        }
        __syncthreads();
    }

    int n = min(cnt, CAND_CAP);
    const ull* src = ck;
    int m = n;

    if (n > DIRECT_MAX){
        // ---- radix-select fallback (rare) -------------------------------
        unsigned prefix = 0u;
        int shift = 24;
        #pragma unroll 1
        for (int pass = 0; pass < 4; pass++){
            if (t < 256) hist[t] = 0u;
            __syncthreads();
            for (int j = t; j < n; j += NT){
                unsigned key = (unsigned)(ck[j] >> 32);
                bool act = (pass == 0) || ((key >> (shift + 8)) == prefix);
                if (act) atomicAdd(&hist[(key >> shift) & 255u], 1u);
            }
            __syncthreads();
            if (t == 0){
                int rem = s_remaining;
                int cum = 0, d = 255;
                for (int dd = 255; dd >= 0; dd--){
                    cum += (int)hist[dd];
                    if (cum >= rem){ d = dd; break; }
                }
                int above_inc = cum - (int)hist[d];
                s_total     = (K_TOP - rem) + cum;
                s_remaining = rem - above_inc;
                s_prefix    = (s_prefix << 8) | (unsigned)d;
            }
            __syncthreads();
            prefix = s_prefix;
            if (s_total <= SBUF || shift == 0) break;
            shift -= 8;
        }
        for (int j = t; j < n; j += NT){
            ull p = ck[j];
            if (((unsigned)(p >> 32) >> shift) >= prefix){
                int q = atomicAdd(&scnt, 1);
                if (q < SBUF) u.sk[q] = p;
            }
        }
        __syncthreads();
        src = u.sk; m = min(scnt, SBUF);
    }

    // pad slots, then exact parallel rank (value desc, idx asc) -> g_pk
    if (t < K_TOP) g_pk[bc * K_TOP + t] = ((ull)0x80000000u << 32) | 0xFFFFFFFFull;
    __syncthreads();
    for (int i = t; i < m; i += NT){
        ull mine = src[i];
        int r = 0;
        for (int jj = 0; jj < m; jj++) r += (src[jj] > mine);   // smem broadcast
        if (r < K_TOP) g_pk[bc * K_TOP + r] = mine;
    }

    // ---- Stage 2 handoff: last CTA of the batch merges ------------------
    __syncthreads();
    __threadfence();                              // publish g_pk slice
    if (t == 0) s_arrive = atomicAdd(&g_bar[b], 1);
    __syncthreads();
    if (s_arrive != NC - 1) return;               // not the last arriver
    __threadfence();                              // see peers' g_pk writes

    // load all 3 channel lists (plain global loads; no stale L1 possible)
    if (t < NC*K_TOP) spk[t] = g_pk[b * NC * K_TOP + t];
    __syncthreads();

    // rank on VALUE ONLY; ties -> lower flat position (lax.top_k stage 2)
    if (t < NC*K_TOP){
        ull mine = spk[t];
        unsigned mk = (unsigned)(mine >> 32);
        int r = 0;
        #pragma unroll 10
        for (int jj = 0; jj < NC*K_TOP; jj++){
            unsigned ok = (unsigned)(spk[jj] >> 32);
            r += (ok > mk) || (ok == mk && jj < t);
        }
        if (r < K_TOP){
            int cls = t / K_TOP;
            unsigned idx = ~((unsigned)mine);
            rpk[r] = ((ull)mk << 32) | ((unsigned)cls << 20) | idx;
        }
    }
    __syncthreads();

    // single-round cooperative gather: 600 threads, one load each
    if (t < K_TOP * 12){
        int det  = t / 12;
        int comp = t - det * 12;
        ull p = rpk[det];
        if (k2f((unsigned)(p >> 32)) > DET_TH){
            int hw = (int)(p & 0xFFFFFu);
            sreg[det][comp] = __ldg(regr + ((size_t)b * 12 + comp) * NHW + hw);
        }
    }
    __syncthreads();

    if (t < K_TOP){
        const int det = b * K_TOP + t;
        ull p = rpk[t];
        float score = k2f((unsigned)(p >> 32));
        float* o = out + (size_t)det * 14;

        if (!(score > DET_TH)){
            #pragma unroll
            for (int i = 0; i < 14; i++) o[i] = 0.0f;
        } else {
            int cls = (int)((p >> 20) & 3u);
            int hw  = (int)(p & 0xFFFFFu);
            float xs = (float)(hw % NW);
            float ys = (float)(hw / NW);

            float reg[12];
            #pragma unroll
            for (int r = 0; r < 12; r++) reg[r] = sreg[t][r];

            float Ti[9], Ki[9], Tm[9], Km[9];
            #pragma unroll
            for (int i = 0; i < 9; i++){ Tm[i] = __ldg(trans + b*9 + i); Km[i] = __ldg(calib + b*9 + i); }
            inv3(Tm, Ti);
            inv3(Km, Ki);

            float depth = reg[0] * 16.32f + 28.01f;
            float px = xs + reg[1], py = ys + reg[2];
            float t0 = (Ti[0]*px + Ti[1]*py + Ti[2]) * depth;
            float t1 = (Ti[3]*px + Ti[4]*py + Ti[5]) * depth;
            float t2 = (Ti[6]*px + Ti[7]*py + Ti[8]) * depth;
            float l0 = Ki[0]*t0 + Ki[1]*t1 + Ki[2]*t2;
            float l1 = Ki[3]*t0 + Ki[4]*t1 + Ki[5]*t2;
            float l2 = Ki[6]*t0 + Ki[7]*t1 + Ki[8]*t2;

            float d0 = expf(reg[3]) * __ldg(dimref + cls*3 + 0);
            float d1 = expf(reg[4]) * __ldg(dimref + cls*3 + 1);
            float d2 = expf(reg[5]) * __ldg(dimref + cls*3 + 2);
            l1 += d1 * 0.5f;

            float ray   = atanf(l0 / (l2 + 1e-7f));
            float alpha = atanf(reg[6] / (reg[7] + 1e-7f));
            alpha += (reg[7] >= 0.0f) ? -PI_F*0.5f : PI_F*0.5f;
            float roty = wrap_pi(alpha + ray);     // pre-wrap alpha, per ref
            alpha = wrap_pi(alpha);

            float cx = xs + reg[8], cy = ys + reg[9];
            float ltx = cx - reg[10]*0.5f, lty = cy - reg[11]*0.5f;
            float rbx = cx + reg[10]*0.5f, rby = cy + reg[11]*0.5f;
            float b0 = Ti[0]*ltx + Ti[1]*lty + Ti[2];
            float b1 = Ti[3]*ltx + Ti[4]*lty + Ti[5];
            float b2 = Ti[0]*rbx + Ti[1]*rby + Ti[2];
            float b3 = Ti[3]*rbx + Ti[4]*rby + Ti[5];

            o[0]  = (float)cls;
            o[1]  = alpha;
            o[2]  = b0; o[3] = b1; o[4] = b2; o[5] = b3;
            o[6]  = d1; o[7] = d2; o[8] = d0;      // roll(dims3d, -1)
            o[9]  = l0; o[10] = l1; o[11] = l2;
            o[12] = roty;
            o[13] = score;
        }
    }

    // reset the batch counter for the next (graph-replayed) launch
    if (t == 0) g_bar[b] = 0;
}

// ---------------------------------------------------------------------------
extern "C" void kernel_launch(void* const* d_in, const int* in_sizes, int n_in,
                              void* d_out, int out_size){
    const float* heat   = (const float*)d_in[0];
    const float* regr   = (const float*)d_in[1];
    const float* calib  = (const float*)d_in[2];
    const float* trans  = (const float*)d_in[3];
    const float* dimref = (const float*)d_in[4];
    float* out = (float*)d_out;

    postproc_kernel<<<NB * NC, NT>>>(heat, regr, calib, trans, dimref, out);
}